// round 1
// baseline (speedup 1.0000x reference)
#include <cuda_runtime.h>
#include <math.h>

#define N_NODES 100000
#define E_MAX   3200000
#define D       256
#define EPSF    1e-5f

// ---------------- static scratch (no allocations allowed) ----------------
__device__ float g_htan[(size_t)N_NODES * D];   // h_tan  [N, 256]
__device__ int   g_cnt[N_NODES];                // per-row edge counts
__device__ int   g_rowstart[N_NODES + 1];       // CSR offsets
__device__ int   g_cursor[N_NODES];             // scatter cursors
__device__ int   g_ecol[E_MAX];                 // CSR col indices
__device__ float g_eval[E_MAX];                 // CSR edge values
__device__ float g_bhyp[D];                     // exp_map_0(bias)
__device__ float g_consts[4];                   // c, sqrt_c, bb

// ---------------- prep: c, sqrt_c, b_hyp, ||b_hyp||^2 ----------------
__global__ void prep_kernel(const float* __restrict__ bias,
                            const float* __restrict__ c_theta) {
    __shared__ float red[8];
    int t = threadIdx.x;
    float ct = c_theta[0];
    float c = log1pf(expf(ct));           // softplus
    float sqrt_c = sqrtf(c);
    float b = bias[t];

    // reduce ||bias||^2 over 256 threads
    float s = b * b;
    #pragma unroll
    for (int o = 16; o; o >>= 1) s += __shfl_xor_sync(0xffffffffu, s, o);
    if ((t & 31) == 0) red[t >> 5] = s;
    __syncthreads();
    float tot = 0.f;
    #pragma unroll
    for (int i = 0; i < 8; i++) tot += red[i];

    float nb = fmaxf(sqrtf(tot), EPSF);
    float f  = tanhf(sqrt_c * nb) / (sqrt_c * nb);
    float bh = f * b;
    g_bhyp[t] = bh;
    __syncthreads();

    // reduce ||b_hyp||^2
    float s2 = bh * bh;
    #pragma unroll
    for (int o = 16; o; o >>= 1) s2 += __shfl_xor_sync(0xffffffffu, s2, o);
    if ((t & 31) == 0) red[t >> 5] = s2;
    __syncthreads();
    if (t == 0) {
        float bb = 0.f;
        #pragma unroll
        for (int i = 0; i < 8; i++) bb += red[i];
        g_consts[0] = c;
        g_consts[1] = sqrt_c;
        g_consts[2] = bb;
    }
}

// ---------------- GEMM (32x256 tile) + fused hyperbolic epilogue ----------------
#define BM 32
#define KC 32

__device__ __forceinline__ float warp_sum(float v) {
    #pragma unroll
    for (int o = 16; o; o >>= 1) v += __shfl_xor_sync(0xffffffffu, v, o);
    return v;
}

__global__ void __launch_bounds__(256) gemm_epi_kernel(const float* __restrict__ x,
                                                       const float* __restrict__ W) {
    __shared__ float xs[BM * KC];        // 4 KB
    __shared__ float ws[KC * D];         // 32 KB
    int t  = threadIdx.x;
    int tx = t & 31;                     // col group
    int ty = t >> 5;                     // warp id -> 4 rows
    int rb = blockIdx.x * BM;

    float acc[4][8];
    #pragma unroll
    for (int i = 0; i < 4; i++)
        #pragma unroll
        for (int j = 0; j < 8; j++) acc[i][j] = 0.f;

    int lrow = t >> 3;                   // 0..31
    int lk4  = (t & 7) * 4;              // 0,4,...,28

    for (int kb = 0; kb < D; kb += KC) {
        // x tile: 32 rows x 32 k
        *(float4*)&xs[lrow * KC + lk4] =
            *(const float4*)&x[(size_t)(rb + lrow) * D + kb + lk4];
        // W tile: rows kb..kb+31, all 256 cols (contiguous 32 KB chunk)
        #pragma unroll
        for (int i = 0; i < 8; i++) {
            int idx = (t + i * 256) * 4;
            *(float4*)&ws[idx] = *(const float4*)&W[(size_t)kb * D + idx];
        }
        __syncthreads();

        #pragma unroll 8
        for (int kk = 0; kk < KC; kk++) {
            float4 w0 = *(float4*)&ws[kk * D + tx * 8];
            float4 w1 = *(float4*)&ws[kk * D + tx * 8 + 4];
            float xv[4];
            #pragma unroll
            for (int i = 0; i < 4; i++) xv[i] = xs[(ty * 4 + i) * KC + kk];
            #pragma unroll
            for (int i = 0; i < 4; i++) {
                acc[i][0] = fmaf(xv[i], w0.x, acc[i][0]);
                acc[i][1] = fmaf(xv[i], w0.y, acc[i][1]);
                acc[i][2] = fmaf(xv[i], w0.z, acc[i][2]);
                acc[i][3] = fmaf(xv[i], w0.w, acc[i][3]);
                acc[i][4] = fmaf(xv[i], w1.x, acc[i][4]);
                acc[i][5] = fmaf(xv[i], w1.y, acc[i][5]);
                acc[i][6] = fmaf(xv[i], w1.z, acc[i][6]);
                acc[i][7] = fmaf(xv[i], w1.w, acc[i][7]);
            }
        }
        __syncthreads();
    }

    // ---- epilogue: exp_map_0 -> mobius_add(b_hyp) -> project -> log_map_0 ----
    float c      = g_consts[0];
    float sqrt_c = g_consts[1];
    float bb     = g_consts[2];
    float4 bhv0 = *(const float4*)&g_bhyp[tx * 8];
    float4 bhv1 = *(const float4*)&g_bhyp[tx * 8 + 4];
    float bh[8] = {bhv0.x, bhv0.y, bhv0.z, bhv0.w, bhv1.x, bhv1.y, bhv1.z, bhv1.w};

    #pragma unroll
    for (int i = 0; i < 4; i++) {
        int row = rb + ty * 4 + i;
        float* a = acc[i];

        // ||z||^2
        float szz = 0.f;
        #pragma unroll
        for (int j = 0; j < 8; j++) szz += a[j] * a[j];
        szz = warp_sum(szz);

        float n  = fmaxf(sqrtf(szz), EPSF);
        float f1 = tanhf(sqrt_c * n) / (sqrt_c * n);

        float zh[8];
        #pragma unroll
        for (int j = 0; j < 8; j++) zh[j] = f1 * a[j];
        float aa = f1 * f1 * szz;                 // ||z_hyp||^2

        // <z_hyp, b_hyp>
        float ab = 0.f;
        #pragma unroll
        for (int j = 0; j < 8; j++) ab += zh[j] * bh[j];
        ab = warp_sum(ab);

        float tc   = 1.f + 2.f * c * ab;
        float numa = tc + c * bb;
        float numb = 1.f - c * aa;
        float den  = fmaxf(tc + c * c * aa * bb, EPSF);
        float inv  = 1.f / den;

        float h[8];
        float hh = 0.f;
        #pragma unroll
        for (int j = 0; j < 8; j++) {
            h[j] = (numa * zh[j] + numb * bh[j]) * inv;
            hh += h[j] * h[j];
        }
        hh = warp_sum(hh);

        float nh   = fmaxf(sqrtf(hh), EPSF);
        float maxn = (1.f - EPSF) / sqrt_c;
        float sc   = (nh > maxn) ? (maxn / nh) : 1.f;

        float n2  = fmaxf(nh * sc, EPSF);
        float arg = fminf(sqrt_c * n2, 1.f - EPSF);
        float f2  = atanhf(arg) / (sqrt_c * n2) * sc;

        float4 o0, o1;
        o0.x = f2 * h[0]; o0.y = f2 * h[1]; o0.z = f2 * h[2]; o0.w = f2 * h[3];
        o1.x = f2 * h[4]; o1.y = f2 * h[5]; o1.z = f2 * h[6]; o1.w = f2 * h[7];
        float* dst = &g_htan[(size_t)row * D + tx * 8];
        *(float4*)dst       = o0;
        *(float4*)(dst + 4) = o1;
    }
}

// ---------------- CSR build ----------------
__global__ void zero_cnt_kernel(int n) {
    for (int i = blockIdx.x * blockDim.x + threadIdx.x; i < n;
         i += gridDim.x * blockDim.x)
        g_cnt[i] = 0;
}

__global__ void hist_kernel(const int* __restrict__ rows, int e) {
    for (int i = blockIdx.x * blockDim.x + threadIdx.x; i < e;
         i += gridDim.x * blockDim.x)
        atomicAdd(&g_cnt[rows[i]], 1);
}

__global__ void __launch_bounds__(1024) scan_kernel(int n) {
    __shared__ int ssum[1024];
    int t = threadIdx.x;
    int per = (n + 1023) / 1024;
    int base = t * per;
    int lim  = min(base + per, n);

    int s = 0;
    for (int i = base; i < lim; i++) s += g_cnt[i];
    ssum[t] = s;
    __syncthreads();
    // Hillis-Steele inclusive scan
    for (int o = 1; o < 1024; o <<= 1) {
        int v = (t >= o) ? ssum[t - o] : 0;
        __syncthreads();
        ssum[t] += v;
        __syncthreads();
    }
    int run = (t == 0) ? 0 : ssum[t - 1];   // exclusive offset
    for (int i = base; i < lim; i++) {
        g_rowstart[i] = run;
        g_cursor[i]   = run;
        run += g_cnt[i];
    }
    if (t == 1023) g_rowstart[n] = ssum[1023];
}

__global__ void scatter_kernel(const int* __restrict__ rows,
                               const int* __restrict__ cols,
                               const float* __restrict__ vals, int e) {
    for (int i = blockIdx.x * blockDim.x + threadIdx.x; i < e;
         i += gridDim.x * blockDim.x) {
        int r = rows[i];
        int p = atomicAdd(&g_cursor[r], 1);
        g_ecol[p] = cols[i];
        g_eval[p] = vals[i];
    }
}

// ---------------- aggregation: warp per row, registers, no atomics ----------------
__device__ __forceinline__ void fma4(float4& a, float v, const float4& b) {
    a.x = fmaf(v, b.x, a.x);
    a.y = fmaf(v, b.y, a.y);
    a.z = fmaf(v, b.z, a.z);
    a.w = fmaf(v, b.w, a.w);
}

__global__ void __launch_bounds__(256) aggregate_kernel(float* __restrict__ out, int n) {
    int warp = (blockIdx.x * blockDim.x + threadIdx.x) >> 5;
    int lane = threadIdx.x & 31;
    if (warp >= n) return;

    int s = g_rowstart[warp];
    int e = g_rowstart[warp + 1];

    float4 a0 = {0.f, 0.f, 0.f, 0.f};
    float4 a1 = {0.f, 0.f, 0.f, 0.f};

    int i = s;
    for (; i + 1 < e; i += 2) {
        int   c0 = g_ecol[i],   c1 = g_ecol[i + 1];
        float v0 = g_eval[i],   v1 = g_eval[i + 1];
        const float4* p0 = (const float4*)(g_htan + (size_t)c0 * D) + lane * 2;
        const float4* p1 = (const float4*)(g_htan + (size_t)c1 * D) + lane * 2;
        float4 x0 = p0[0], y0 = p0[1];
        float4 x1 = p1[0], y1 = p1[1];
        fma4(a0, v0, x0); fma4(a1, v0, y0);
        fma4(a0, v1, x1); fma4(a1, v1, y1);
    }
    if (i < e) {
        int   c0 = g_ecol[i];
        float v0 = g_eval[i];
        const float4* p0 = (const float4*)(g_htan + (size_t)c0 * D) + lane * 2;
        fma4(a0, v0, p0[0]); fma4(a1, v0, p0[1]);
    }

    a0.x = fmaxf(a0.x, 0.f); a0.y = fmaxf(a0.y, 0.f);
    a0.z = fmaxf(a0.z, 0.f); a0.w = fmaxf(a0.w, 0.f);
    a1.x = fmaxf(a1.x, 0.f); a1.y = fmaxf(a1.y, 0.f);
    a1.z = fmaxf(a1.z, 0.f); a1.w = fmaxf(a1.w, 0.f);

    float4* dst = (float4*)(out + (size_t)warp * D) + lane * 2;
    dst[0] = a0;
    dst[1] = a1;
}

// ---------------- launch ----------------
extern "C" void kernel_launch(void* const* d_in, const int* in_sizes, int n_in,
                              void* d_out, int out_size) {
    const float* x       = (const float*)d_in[0];
    const int*   rows    = (const int*)d_in[1];
    const int*   cols    = (const int*)d_in[2];
    const float* vals    = (const float*)d_in[3];
    const float* W       = (const float*)d_in[4];
    const float* bias    = (const float*)d_in[5];
    const float* c_theta = (const float*)d_in[6];
    float* out = (float*)d_out;

    int n = in_sizes[0] / D;   // 100000
    int e = in_sizes[1];       // 3200000

    prep_kernel<<<1, 256>>>(bias, c_theta);
    gemm_epi_kernel<<<(n + BM - 1) / BM, 256>>>(x, W);

    zero_cnt_kernel<<<512, 256>>>(n);
    hist_kernel<<<1024, 256>>>(rows, e);
    scan_kernel<<<1, 1024>>>(n);
    scatter_kernel<<<1024, 256>>>(rows, cols, vals, e);

    aggregate_kernel<<<(n * 32 + 255) / 256, 256>>>(out, n);
}

// round 2
// speedup vs baseline: 1.2849x; 1.2849x over previous
#include <cuda_runtime.h>
#include <math.h>
#include <stdint.h>

#define N_NODES 100000
#define E_MAX   3200000
#define D       256
#define EPSF    1e-5f
#define BM      64

// ---------------- static scratch (no allocations allowed) ----------------
__device__ float g_htan[(size_t)N_NODES * D];   // h_tan  [N, 256]
__device__ int   g_cnt[N_NODES];
__device__ int   g_rowstart[N_NODES + 1];
__device__ int   g_cursor[N_NODES];
__device__ int   g_ecol[E_MAX];
__device__ float g_eval[E_MAX];
__device__ float g_bhyp[D];
__device__ float g_consts[4];                   // c, sqrt_c, bb
// W in mma-fragment layout, tf32 hi/lo: [kb(8)][wn(4)][nt(8)][ks(4)][lane(32)][4]
__device__ float g_wfrag[8 * 4 * 8 * 4 * 32 * 4];

__device__ __forceinline__ uint32_t f2tf32(float x) {
    uint32_t r;
    asm("cvt.rna.tf32.f32 %0, %1;" : "=r"(r) : "f"(x));
    return r;
}
__device__ __forceinline__ float warp_sum(float v) {
    #pragma unroll
    for (int o = 16; o; o >>= 1) v += __shfl_xor_sync(0xffffffffu, v, o);
    return v;
}
__device__ __forceinline__ void mma_tf32(float* c, const uint32_t* a,
                                         uint32_t b0, uint32_t b1) {
    asm volatile(
        "mma.sync.aligned.m16n8k8.row.col.f32.tf32.tf32.f32 "
        "{%0,%1,%2,%3}, {%4,%5,%6,%7}, {%8,%9}, {%0,%1,%2,%3};\n"
        : "+f"(c[0]), "+f"(c[1]), "+f"(c[2]), "+f"(c[3])
        : "r"(a[0]), "r"(a[1]), "r"(a[2]), "r"(a[3]), "r"(b0), "r"(b1));
}

// ---------------- prep: c, sqrt_c, b_hyp, ||b_hyp||^2 ----------------
__global__ void prep_kernel(const float* __restrict__ bias,
                            const float* __restrict__ c_theta) {
    __shared__ float red[8];
    int t = threadIdx.x;
    float ct = c_theta[0];
    float c = log1pf(expf(ct));           // softplus
    float sqrt_c = sqrtf(c);
    float b = bias[t];

    float s = b * b;
    s = warp_sum(s);
    if ((t & 31) == 0) red[t >> 5] = s;
    __syncthreads();
    float tot = 0.f;
    #pragma unroll
    for (int i = 0; i < 8; i++) tot += red[i];

    float nb = fmaxf(sqrtf(tot), EPSF);
    float f  = tanhf(sqrt_c * nb) / (sqrt_c * nb);
    float bh = f * b;
    g_bhyp[t] = bh;
    __syncthreads();

    float s2 = bh * bh;
    s2 = warp_sum(s2);
    if ((t & 31) == 0) red[t >> 5] = s2;
    __syncthreads();
    if (t == 0) {
        float bb = 0.f;
        #pragma unroll
        for (int i = 0; i < 8; i++) bb += red[i];
        g_consts[0] = c;
        g_consts[1] = sqrt_c;
        g_consts[2] = bb;
    }
}

// ---------------- W split into tf32 hi/lo fragment layout ----------------
__global__ void prep_w_kernel(const float* __restrict__ W) {
    int t = blockIdx.x * blockDim.x + threadIdx.x;   // 0..32767
    int lane = t & 31;
    int ks = (t >> 5) & 3;
    int nt = (t >> 7) & 7;
    int wn = (t >> 10) & 3;
    int kb = (t >> 12) & 7;
    int g = lane >> 2, tig = lane & 3;
    int ncol = wn * 64 + nt * 8 + g;
    int k0 = kb * 32 + ks * 8 + tig;
    float w0 = W[(size_t)k0 * D + ncol];
    float w1 = W[(size_t)(k0 + 4) * D + ncol];
    uint32_t h0 = f2tf32(w0), h1 = f2tf32(w1);
    float hf0 = __uint_as_float(h0), hf1 = __uint_as_float(h1);
    uint32_t l0 = f2tf32(w0 - hf0), l1 = f2tf32(w1 - hf1);
    float4 v;
    v.x = hf0; v.y = hf1;
    v.z = __uint_as_float(l0); v.w = __uint_as_float(l1);
    ((float4*)g_wfrag)[t] = v;
}

// ---------------- GEMM (tf32 3-term split) + fused hyperbolic epilogue ----------------
// smem: A hi [64][36] + A lo [64][36] + B frags 16384 floats; z aliases all of it.
#define APAD 36
#define SM_AH 0
#define SM_AL (64 * APAD)
#define SM_B  (2 * 64 * APAD)
#define SM_FLOATS (2 * 64 * APAD + 16384)
#define ZPAD 260

__global__ void __launch_bounds__(256, 2)
gemm_epi_kernel(const float* __restrict__ x, int n) {
    extern __shared__ float sm[];
    int t = threadIdx.x;
    int lane = t & 31, wid = t >> 5;
    int wm = wid & 1, wn = wid >> 1;       // 2 x 4 warp grid
    int g = lane >> 2, tig = lane & 3;
    int rb = blockIdx.x * BM;

    float acc[2][8][4];
    #pragma unroll
    for (int mt = 0; mt < 2; mt++)
        #pragma unroll
        for (int nt = 0; nt < 8; nt++)
            #pragma unroll
            for (int i = 0; i < 4; i++) acc[mt][nt][i] = 0.f;

    int arow = t >> 2;                     // 0..63
    int acol = (t & 3) * 8;                // 0,8,16,24

    for (int kb = 0; kb < 8; kb++) {
        // ---- stage A: load x[64 x 32], split hi/lo ----
        int gr = min(rb + arow, n - 1);
        const float* xp = x + (size_t)gr * D + kb * 32 + acol;
        float4 v0 = *(const float4*)xp;
        float4 v1 = *(const float4*)(xp + 4);
        float vv[8] = {v0.x, v0.y, v0.z, v0.w, v1.x, v1.y, v1.z, v1.w};
        float hi[8], lo[8];
        #pragma unroll
        for (int j = 0; j < 8; j++) {
            hi[j] = __uint_as_float(f2tf32(vv[j]));
            lo[j] = __uint_as_float(f2tf32(vv[j] - hi[j]));
        }
        float* ah = &sm[SM_AH + arow * APAD + acol];
        float* al = &sm[SM_AL + arow * APAD + acol];
        *(float4*)ah       = make_float4(hi[0], hi[1], hi[2], hi[3]);
        *(float4*)(ah + 4) = make_float4(hi[4], hi[5], hi[6], hi[7]);
        *(float4*)al       = make_float4(lo[0], lo[1], lo[2], lo[3]);
        *(float4*)(al + 4) = make_float4(lo[4], lo[5], lo[6], lo[7]);

        // ---- stage B: copy 64KB fragment chunk ----
        const float4* bs = ((const float4*)g_wfrag) + (size_t)kb * 4096;
        float4* bd = (float4*)&sm[SM_B];
        #pragma unroll
        for (int i = 0; i < 16; i++) bd[t + i * 256] = bs[t + i * 256];
        __syncthreads();

        // ---- compute ----
        #pragma unroll
        for (int ks = 0; ks < 4; ks++) {
            uint32_t afh[2][4], afl[2][4];
            #pragma unroll
            for (int mt = 0; mt < 2; mt++) {
                int r0 = wm * 32 + mt * 16 + g;
                int k0 = ks * 8 + tig;
                afh[mt][0] = __float_as_uint(sm[SM_AH + r0 * APAD + k0]);
                afh[mt][1] = __float_as_uint(sm[SM_AH + (r0 + 8) * APAD + k0]);
                afh[mt][2] = __float_as_uint(sm[SM_AH + r0 * APAD + k0 + 4]);
                afh[mt][3] = __float_as_uint(sm[SM_AH + (r0 + 8) * APAD + k0 + 4]);
                afl[mt][0] = __float_as_uint(sm[SM_AL + r0 * APAD + k0]);
                afl[mt][1] = __float_as_uint(sm[SM_AL + (r0 + 8) * APAD + k0]);
                afl[mt][2] = __float_as_uint(sm[SM_AL + r0 * APAD + k0 + 4]);
                afl[mt][3] = __float_as_uint(sm[SM_AL + (r0 + 8) * APAD + k0 + 4]);
            }
            #pragma unroll
            for (int nt = 0; nt < 8; nt++) {
                float4 bf = *(float4*)&sm[SM_B + ((((wn * 8 + nt) * 4 + ks) * 32 + lane) << 2)];
                uint32_t bh0 = __float_as_uint(bf.x), bh1 = __float_as_uint(bf.y);
                uint32_t bl0 = __float_as_uint(bf.z), bl1 = __float_as_uint(bf.w);
                #pragma unroll
                for (int mt = 0; mt < 2; mt++) {
                    mma_tf32(acc[mt][nt], afh[mt], bh0, bh1);
                    mma_tf32(acc[mt][nt], afl[mt], bh0, bh1);
                    mma_tf32(acc[mt][nt], afh[mt], bl0, bl1);
                }
            }
        }
        __syncthreads();
    }

    // ---- dump accumulators to smem z[64][260] (aliases A/B buffers) ----
    float* z = sm;
    #pragma unroll
    for (int mt = 0; mt < 2; mt++)
        #pragma unroll
        for (int nt = 0; nt < 8; nt++) {
            int r0 = wm * 32 + mt * 16 + g;
            int col = wn * 64 + nt * 8 + 2 * tig;
            *(float2*)&z[r0 * ZPAD + col]       = make_float2(acc[mt][nt][0], acc[mt][nt][1]);
            *(float2*)&z[(r0 + 8) * ZPAD + col] = make_float2(acc[mt][nt][2], acc[mt][nt][3]);
        }
    __syncthreads();

    // ---- epilogue: warp per row (8 rows/warp), lanes over 256 cols ----
    float c      = g_consts[0];
    float sqrt_c = g_consts[1];
    float bb     = g_consts[2];
    float4 bhv0 = *(const float4*)&g_bhyp[lane * 8];
    float4 bhv1 = *(const float4*)&g_bhyp[lane * 8 + 4];
    float bh[8] = {bhv0.x, bhv0.y, bhv0.z, bhv0.w, bhv1.x, bhv1.y, bhv1.z, bhv1.w};

    #pragma unroll
    for (int i = 0; i < 8; i++) {
        int lrow = wid * 8 + i;
        int grow = rb + lrow;
        float4 z0 = *(float4*)&z[lrow * ZPAD + lane * 8];
        float4 z1 = *(float4*)&z[lrow * ZPAD + lane * 8 + 4];
        float a[8] = {z0.x, z0.y, z0.z, z0.w, z1.x, z1.y, z1.z, z1.w};

        float szz = 0.f;
        #pragma unroll
        for (int j = 0; j < 8; j++) szz += a[j] * a[j];
        szz = warp_sum(szz);

        float nrm = fmaxf(sqrtf(szz), EPSF);
        float f1  = tanhf(sqrt_c * nrm) / (sqrt_c * nrm);

        float zh[8];
        #pragma unroll
        for (int j = 0; j < 8; j++) zh[j] = f1 * a[j];
        float aa = f1 * f1 * szz;

        float ab = 0.f;
        #pragma unroll
        for (int j = 0; j < 8; j++) ab += zh[j] * bh[j];
        ab = warp_sum(ab);

        float tc   = 1.f + 2.f * c * ab;
        float numa = tc + c * bb;
        float numb = 1.f - c * aa;
        float den  = fmaxf(tc + c * c * aa * bb, EPSF);
        float inv  = 1.f / den;

        float h[8];
        float hh = 0.f;
        #pragma unroll
        for (int j = 0; j < 8; j++) {
            h[j] = (numa * zh[j] + numb * bh[j]) * inv;
            hh += h[j] * h[j];
        }
        hh = warp_sum(hh);

        float nh   = fmaxf(sqrtf(hh), EPSF);
        float maxn = (1.f - EPSF) / sqrt_c;
        float sc   = (nh > maxn) ? (maxn / nh) : 1.f;

        float n2  = fmaxf(nh * sc, EPSF);
        float arg = fminf(sqrt_c * n2, 1.f - EPSF);
        float f2  = atanhf(arg) / (sqrt_c * n2) * sc;

        if (grow < n) {
            float4 o0, o1;
            o0.x = f2 * h[0]; o0.y = f2 * h[1]; o0.z = f2 * h[2]; o0.w = f2 * h[3];
            o1.x = f2 * h[4]; o1.y = f2 * h[5]; o1.z = f2 * h[6]; o1.w = f2 * h[7];
            float* dst = &g_htan[(size_t)grow * D + lane * 8];
            *(float4*)dst       = o0;
            *(float4*)(dst + 4) = o1;
        }
    }
}

// ---------------- CSR build ----------------
__global__ void zero_cnt_kernel(int n) {
    for (int i = blockIdx.x * blockDim.x + threadIdx.x; i < n;
         i += gridDim.x * blockDim.x)
        g_cnt[i] = 0;
}

__global__ void hist_kernel(const int* __restrict__ rows, int e) {
    for (int i = blockIdx.x * blockDim.x + threadIdx.x; i < e;
         i += gridDim.x * blockDim.x)
        atomicAdd(&g_cnt[rows[i]], 1);
}

__global__ void __launch_bounds__(1024) scan_kernel(int n) {
    __shared__ int ssum[1024];
    int t = threadIdx.x;
    int per = (n + 1023) / 1024;
    int base = t * per;
    int lim  = min(base + per, n);

    int s = 0;
    for (int i = base; i < lim; i++) s += g_cnt[i];
    ssum[t] = s;
    __syncthreads();
    for (int o = 1; o < 1024; o <<= 1) {
        int v = (t >= o) ? ssum[t - o] : 0;
        __syncthreads();
        ssum[t] += v;
        __syncthreads();
    }
    int run = (t == 0) ? 0 : ssum[t - 1];
    for (int i = base; i < lim; i++) {
        g_rowstart[i] = run;
        g_cursor[i]   = run;
        run += g_cnt[i];
    }
    if (t == 1023) g_rowstart[n] = ssum[1023];
}

__global__ void scatter_kernel(const int* __restrict__ rows,
                               const int* __restrict__ cols,
                               const float* __restrict__ vals, int e) {
    for (int i = blockIdx.x * blockDim.x + threadIdx.x; i < e;
         i += gridDim.x * blockDim.x) {
        int r = rows[i];
        int p = atomicAdd(&g_cursor[r], 1);
        g_ecol[p] = cols[i];
        g_eval[p] = vals[i];
    }
}

// ---------------- aggregation: warp per row, registers, no atomics ----------------
__device__ __forceinline__ void fma4(float4& a, float v, const float4& b) {
    a.x = fmaf(v, b.x, a.x);
    a.y = fmaf(v, b.y, a.y);
    a.z = fmaf(v, b.z, a.z);
    a.w = fmaf(v, b.w, a.w);
}

__global__ void __launch_bounds__(256) aggregate_kernel(float* __restrict__ out, int n) {
    int warp = (blockIdx.x * blockDim.x + threadIdx.x) >> 5;
    int lane = threadIdx.x & 31;
    if (warp >= n) return;

    int s = g_rowstart[warp];
    int e = g_rowstart[warp + 1];

    float4 a0 = {0.f, 0.f, 0.f, 0.f};
    float4 a1 = {0.f, 0.f, 0.f, 0.f};

    int i = s;
    for (; i + 3 < e; i += 4) {
        int   c0 = g_ecol[i],     c1 = g_ecol[i + 1];
        int   c2 = g_ecol[i + 2], c3 = g_ecol[i + 3];
        float v0 = g_eval[i],     v1 = g_eval[i + 1];
        float v2 = g_eval[i + 2], v3 = g_eval[i + 3];
        const float4* p0 = (const float4*)(g_htan + (size_t)c0 * D) + lane * 2;
        const float4* p1 = (const float4*)(g_htan + (size_t)c1 * D) + lane * 2;
        const float4* p2 = (const float4*)(g_htan + (size_t)c2 * D) + lane * 2;
        const float4* p3 = (const float4*)(g_htan + (size_t)c3 * D) + lane * 2;
        float4 x0 = p0[0], y0 = p0[1];
        float4 x1 = p1[0], y1 = p1[1];
        float4 x2 = p2[0], y2 = p2[1];
        float4 x3 = p3[0], y3 = p3[1];
        fma4(a0, v0, x0); fma4(a1, v0, y0);
        fma4(a0, v1, x1); fma4(a1, v1, y1);
        fma4(a0, v2, x2); fma4(a1, v2, y2);
        fma4(a0, v3, x3); fma4(a1, v3, y3);
    }
    for (; i < e; i++) {
        int   c0 = g_ecol[i];
        float v0 = g_eval[i];
        const float4* p0 = (const float4*)(g_htan + (size_t)c0 * D) + lane * 2;
        fma4(a0, v0, p0[0]); fma4(a1, v0, p0[1]);
    }

    a0.x = fmaxf(a0.x, 0.f); a0.y = fmaxf(a0.y, 0.f);
    a0.z = fmaxf(a0.z, 0.f); a0.w = fmaxf(a0.w, 0.f);
    a1.x = fmaxf(a1.x, 0.f); a1.y = fmaxf(a1.y, 0.f);
    a1.z = fmaxf(a1.z, 0.f); a1.w = fmaxf(a1.w, 0.f);

    float4* dst = (float4*)(out + (size_t)warp * D) + lane * 2;
    dst[0] = a0;
    dst[1] = a1;
}

// ---------------- launch ----------------
extern "C" void kernel_launch(void* const* d_in, const int* in_sizes, int n_in,
                              void* d_out, int out_size) {
    const float* x       = (const float*)d_in[0];
    const int*   rows    = (const int*)d_in[1];
    const int*   cols    = (const int*)d_in[2];
    const float* vals    = (const float*)d_in[3];
    const float* W       = (const float*)d_in[4];
    const float* bias    = (const float*)d_in[5];
    const float* c_theta = (const float*)d_in[6];
    float* out = (float*)d_out;

    int n = in_sizes[0] / D;   // 100000
    int e = in_sizes[1];       // 3200000

    static int smem_set = 0;
    (void)smem_set;
    cudaFuncSetAttribute(gemm_epi_kernel,
                         cudaFuncAttributeMaxDynamicSharedMemorySize,
                         SM_FLOATS * 4);

    prep_kernel<<<1, 256>>>(bias, c_theta);
    prep_w_kernel<<<128, 256>>>(W);
    gemm_epi_kernel<<<(n + BM - 1) / BM, 256, SM_FLOATS * 4>>>(x, n);

    zero_cnt_kernel<<<512, 256>>>(n);
    hist_kernel<<<1024, 256>>>(rows, e);
    scan_kernel<<<1, 1024>>>(n);
    scatter_kernel<<<1024, 256>>>(rows, cols, vals, e);

    aggregate_kernel<<<(n * 32 + 255) / 256, 256>>>(out, n);
}